// round 15
// baseline (speedup 1.0000x reference)
#include <cuda_runtime.h>
#include <cuda_fp16.h>
#include <cstdint>

// ================= problem constants =================
#define NB   1024
#define IIC  128
#define MGLOB (NB*784)            // 802816 flattened output rows
#define GRID_MAIN 304
#define THREADS 256
#define GUNITS (MGLOB/32)         // 25088 gemm units of 32m x 128i
#define PROWS  (NB*28)            // 28672 prep rows
#define TOTAL_PAIRS (GRID_MAIN*4)

// ticket stream: HEAD prep, then MIDB blocks of [8 prep + 7 gemm], then gemm tail
#define BLOCKS 3584               // PROWS/8
#define LAGB   128
#define HEAD   (8*LAGB)           // 1024
#define MIDB   (BLOCKS-LAGB)      // 3456
#define TICKETS (15*BLOCKS)       // 53760

// ================= scratch =================
__device__ __half g_R[(size_t)PROWS*1024];    // 58.7 MB
__device__ unsigned g_flag[PROWS];            // generation flags (monotonic)
__device__ int g_next;                        // ticket counter
__device__ int g_done;                        // reset coordinator
__device__ unsigned g_cta_ctr;                // monotonic launch/run id source

// ================= smem layout =================
#define WS_B32    (18*8*32*4)                   // 73728 B
#define WS_BYTES  (WS_B32*4)
#define PBUF_B32  512                           // 2KB: one chunk of 32 rows
#define NBUF      4
#define ACT_BYTES (4*NBUF*PBUF_B32*4)           // 32768 B
#define GSH_OFF   (WS_BYTES + ACT_BYTES)        // 106496
#define SM_TOTAL  (GSH_OFF + 32)

__device__ __forceinline__ void mma_f16(float4& d, const uint4& a, uint32_t b0, uint32_t b1) {
    asm volatile(
        "mma.sync.aligned.m16n8k16.row.col.f32.f16.f16.f32 "
        "{%0,%1,%2,%3}, {%4,%5,%6,%7}, {%8,%9}, {%0,%1,%2,%3};"
        : "+f"(d.x), "+f"(d.y), "+f"(d.z), "+f"(d.w)
        : "r"(a.x), "r"(a.y), "r"(a.z), "r"(a.w), "r"(b0), "r"(b1));
}

#define PAIRBAR(p) asm volatile("bar.sync %0, 64;" :: "r"((p) + 1) : "memory")

// ticket decode
__device__ __forceinline__ void decode_ticket(int t, bool& isprep, int& idx) {
    if (t < HEAD) { isprep = true; idx = t; return; }
    const int q = t - HEAD;
    if (q < 15 * MIDB) {
        const int b = q / 15, r = q - b * 15;
        if (r < 8) { isprep = true;  idx = 8 * (LAGB + b) + r; }
        else       { isprep = false; idx = 7 * b + (r - 8); }
    } else {
        isprep = false; idx = 7 * MIDB + (q - 15 * MIDB);
    }
}

// ================= fused kernel =================
__global__ __launch_bounds__(THREADS, 2) void fused_kernel(const float* __restrict__ x,
                                                           const float* __restrict__ Wg,
                                                           float* __restrict__ out) {
    extern __shared__ char smem[];
    uint32_t* wsb = reinterpret_cast<uint32_t*>(smem);
    const uint4* ws4 = reinterpret_cast<const uint4*>(smem);
    int* gsh = reinterpret_cast<int*>(smem + GSH_OFF);          // [0..3] tickets, [4] run

    const int tid  = threadIdx.x;
    const int lane = tid & 31;
    const int w    = tid >> 5;
    const int warp_i = w & 1;
    const int pair   = w >> 1;
    const int wg   = warp_i * 32 + lane;   // 0..63 within pair
    const int gq   = lane >> 2;
    const int tig  = lane & 3;

    uint32_t* pact = reinterpret_cast<uint32_t*>(smem + WS_BYTES) + pair * (NBUF * PBUF_B32);
    float* scr = reinterpret_cast<float*>(pact) + warp_i * 1024;   // epilogue scratch
    float* xs  = reinterpret_cast<float*>(pact);                   // prep scratch (1856 f)

    // run id (same for all CTAs of one launch; monotonic across graph replays)
    if (tid == 0) gsh[4] = (int)(atomicAdd(&g_cta_ctr, 1u) / GRID_MAIN + 1u);

    // ---- weights -> fp16 fragment-ready smem (validated R9-R14) ----
    for (int t = tid; t < WS_B32; t += THREADS) {
        const int reg = t & 3;
        const int ln  = (t >> 2) & 31;
        const int mt  = (t >> 7) & 7;
        const int S   = t >> 10;
        const int r   = (ln >> 2) + ((reg & 1) << 3);
        const int k16 = ((ln & 3) << 1) + ((reg >> 1) << 3);
        const int i   = (mt << 4) + r;
        const int kp  = (S << 4) + k16;
        const int c   = kp >> 5, l = kp & 31;
        const float w0 = Wg[(l * 9 + c) * 128 + i];
        const float w1 = Wg[((l + 1) * 9 + c) * 128 + i];
        const __half2 hv = __floats2half2_rn(w0, w1);
        wsb[t] = *reinterpret_cast<const uint32_t*>(&hv);
    }
    __syncthreads();
    const unsigned run = (unsigned)gsh[4];

    // B-frag swizzled lane offsets
    int lofs[4];
    #pragma unroll
    for (int rr = 0; rr < 4; ++rr)
        lofs[rr] = ((gq ^ (rr << 1)) << 2) + tig;

    // staging identity
    const int srow = lane >> 2;
    const int slot = lane & 3;
    int dstb[2];
    #pragma unroll
    for (int q = 0; q < 2; ++q) {
        const int m_loc = warp_i * 16 + q * 8 + srow;
        dstb[q] = (((slot << 2) + (m_loc >> 3)) << 5)
                + (((m_loc & 7) ^ (slot << 1)) << 2);
    }

    while (true) {
        if (wg == 0) {
            const int t = atomicAdd(&g_next, 1);
            if (t < TICKETS) {
                bool isprep; int idx;
                decode_ticket(t, isprep, idx);
                if (!isprep) {
                    // wait for needed prep rows [lo, hi]
                    const int mb = idx << 5;
                    int lo = mb / 28 - 1;            if (lo < 0) lo = 0;
                    int hi = (mb + 31) / 28 + 1;     if (hi > PROWS - 1) hi = PROWS - 1;
                    for (int p = lo; p <= hi; ++p) {
                        unsigned v;
                        do {
                            asm volatile("ld.acquire.gpu.global.u32 %0, [%1];"
                                         : "=r"(v) : "l"(g_flag + p));
                        } while (v < run);
                    }
                }
            }
            gsh[pair] = t;
        }
        PAIRBAR(pair);
        const int t = gsh[pair];
        if (t >= TICKETS) break;
        bool isprep; int idx;
        decode_ticket(t, isprep, idx);

        if (isprep) {
            // ================= prep one (n,h') row (validated R4-R14 math) =======
            const int n = idx / 28, h = idx - n * 28;
            const float4* x4 = reinterpret_cast<const float4*>(x);
            for (int e = wg; e < 448; e += 64) {
                const int c = e / 7, f = e - c * 7;
                const float4 v = x4[((size_t)(n * 64 + c) * 28 + h) * 7 + f];
                float* dst = &xs[c * 29 + f * 4];
                dst[0] = v.x; dst[1] = v.y; dst[2] = v.z; dst[3] = v.w;
            }
            PAIRBAR(pair);
            __half* Rout = g_R + (size_t)idx * 1024;
            const int lp = wg & 15, l0 = lp << 1;
            const int qg = wg >> 4;                 // 0..3
            #pragma unroll
            for (int r = 0; r < 8; ++r) {
                const int q = r * 4 + qg;
                float v0, v1;
                if (q < 28) {
                    int u1 = q - 1; if (u1 < 0) u1 += 28;
                    int u2 = q - 2; if (u2 < 0) u2 += 28;
                    v0 = xs[l0 * 29 + u1] + xs[(32 + l0) * 29 + u2];
                    v1 = xs[(l0 + 1) * 29 + u1] + xs[(33 + l0) * 29 + u2];
                } else if (q == 28) { v0 = xs[(32 + l0) * 29 + 25]; v1 = xs[(33 + l0) * 29 + 25]; }
                else if (q == 29)   { v0 = xs[l0 * 29 + 27];        v1 = xs[(l0 + 1) * 29 + 27]; }
                else if (q == 30)   { v0 = xs[l0 * 29 + 0];         v1 = xs[(l0 + 1) * 29 + 0];  }
                else                { v0 = xs[(32 + l0) * 29 + 26]; v1 = xs[(33 + l0) * 29 + 26]; }
                *reinterpret_cast<__half2*>(&Rout[q * 32 + l0]) = __floats2half2_rn(v0, v1);
            }
            __threadfence();
            PAIRBAR(pair);
            if (wg == 0)
                asm volatile("st.release.gpu.global.u32 [%0], %1;"
                             :: "l"(g_flag + idx), "r"(run) : "memory");
            continue;
        }

        // ================= GEMM unit (byte-identical R14 path) =================
        const int mbase = idx << 5;

        int hq[2], baseq[2], ikp[2];
        #pragma unroll
        for (int q = 0; q < 2; ++q) {
            const int m_loc = warp_i * 16 + q * 8 + srow;
            const int mg = mbase + m_loc;
            const int n  = mg / 784;
            const int r  = mg - n * 784;
            const int h  = r / 28;
            const int wp = r - h * 28;
            hq[q]    = h;
            baseq[q] = (n * 28 + h) << 10;
            const int ik0 = (wp == 0) ? 28 : (wp == 1) ? 29 : (wp - 1);
            const int ik2 = (wp == 0) ? 30 : (wp == 27) ? 31 : (wp + 1);
            ikp[q] = ik0 | (wp << 5) | (ik2 << 10);
        }

        uint4 sv[2];
        #define LDG_CHUNK(cn)  do {                                              \
            const int jj = ((cn) * 11) >> 5;                                     \
            const int kk = (cn) - jj * 3;                                        \
            _Pragma("unroll")                                                    \
            for (int q = 0; q < 2; ++q) {                                        \
                const int hp = hq[q] + jj - 1;                                   \
                const int ik = (ikp[q] >> (kk * 5)) & 31;                        \
                const int off = baseq[q] + ((jj - 1) << 10) + (ik << 5);         \
                sv[q] = make_uint4(0u, 0u, 0u, 0u);                              \
                if ((unsigned)hp < 28u)                                          \
                    sv[q] = *reinterpret_cast<const uint4*>(g_R + off + (slot << 3)); \
            } } while (0)
        #define STS_CHUNK(cn) do {                                               \
            uint32_t* bufn = pact + ((cn) & 3) * PBUF_B32;                       \
            _Pragma("unroll")                                                    \
            for (int q = 0; q < 2; ++q)                                          \
                *reinterpret_cast<uint4*>(bufn + dstb[q]) = sv[q];               \
            } while (0)

        LDG_CHUNK(0); STS_CHUNK(0);
        LDG_CHUNK(1); STS_CHUNK(1);
        LDG_CHUNK(2);
        PAIRBAR(pair);

        float4 acc[4][4];
        #pragma unroll
        for (int a = 0; a < 4; ++a)
            #pragma unroll
            for (int b = 0; b < 4; ++b)
                acc[a][b] = make_float4(0.f, 0.f, 0.f, 0.f);

        #pragma unroll 1
        for (int c = 0; c < 9; ++c) {
            if (c <= 6) STS_CHUNK(c + 2);
            if (c <= 5) LDG_CHUNK(c + 3);

            const uint32_t* bufc = pact + (c & 3) * PBUF_B32;
            #pragma unroll
            for (int s = 0; s < 2; ++s) {
                const int S = c * 2 + s;
                uint4 afr[4];
                #pragma unroll
                for (int mtl = 0; mtl < 4; ++mtl)
                    afr[mtl] = ws4[((S << 3) + warp_i * 4 + mtl) * 32 + lane];
                const int rr0 = s * 2, rr1 = s * 2 + 1;
                uint2 bfr[4];
                #pragma unroll
                for (int ntl = 0; ntl < 4; ++ntl) {
                    bfr[ntl].x = bufc[(((rr0 << 2) + ntl) << 5) + lofs[rr0]];
                    bfr[ntl].y = bufc[(((rr1 << 2) + ntl) << 5) + lofs[rr1]];
                }
                #pragma unroll
                for (int mtl = 0; mtl < 4; ++mtl)
                    #pragma unroll
                    for (int ntl = 0; ntl < 4; ++ntl)
                        mma_f16(acc[mtl][ntl], afr[mtl], bfr[ntl].x, bfr[ntl].y);
            }

            if ((c & 1) || c == 8) PAIRBAR(pair);
        }

        // epilogue: smem transpose -> full-line STG.128 (R14)
        #pragma unroll
        for (int mtl = 0; mtl < 4; ++mtl) {
            __syncwarp();
            #pragma unroll
            for (int ntl = 0; ntl < 4; ++ntl) {
                const float4 v = acc[mtl][ntl];
                const int m0 = ntl * 8 + (tig << 1);
                const int r0 = gq, r1 = gq + 8;
                *reinterpret_cast<float2*>(&scr[r0 * 36 + ((m0 + (r0 << 2)) & 31)])
                    = make_float2(v.x, v.y);
                *reinterpret_cast<float2*>(&scr[r1 * 36 + ((m0 + (r1 << 2)) & 31)])
                    = make_float2(v.z, v.w);
            }
            __syncwarp();
            const int m8 = lane & 7;
            const int rsl = lane >> 3;
            #pragma unroll
            for (int tt = 0; tt < 4; ++tt) {
                const int row = tt * 4 + rsl;
                const float4 o = *reinterpret_cast<const float4*>(
                    &scr[row * 36 + (((m8 << 2) + (row << 2)) & 31)]);
                const int irow = warp_i * 64 + mtl * 16 + row;
                const int mgo = mbase + (m8 << 2);
                const int n = mgo / 784;
                const int r = mgo - n * 784;
                *reinterpret_cast<float4*>(
                    out + (size_t)n * (IIC * 784) + (size_t)irow * 784 + r) = o;
            }
        }
        #undef LDG_CHUNK
        #undef STS_CHUNK
    }

    // ---- self-reset of ticket counters (deterministic, graph-replay safe) ----
    if (wg == 0) {
        const int old = atomicAdd(&g_done, 1);
        if (old == TOTAL_PAIRS - 1) {
            g_next = 0;
            __threadfence();
            g_done = 0;
        }
    }
}

// ================= launch =================
extern "C" void kernel_launch(void* const* d_in, const int* in_sizes, int n_in,
                              void* d_out, int out_size) {
    const float* x  = (const float*)d_in[0];   // (1024,64,28,28)
    const float* Wg = (const float*)d_in[1];   // (32,3,3,128)
    float* out = (float*)d_out;                // (1024,128,28,28)

    cudaFuncSetAttribute(fused_kernel, cudaFuncAttributeMaxDynamicSharedMemorySize, SM_TOTAL);
    fused_kernel<<<GRID_MAIN, THREADS, SM_TOTAL>>>(x, Wg, out);
}

// round 17
// speedup vs baseline: 1.0895x; 1.0895x over previous
#include <cuda_runtime.h>
#include <cuda_fp16.h>
#include <cstdint>

// ================= problem constants =================
#define NB   1024
#define IIC  128
#define MGLOB (NB*784)            // 802816 flattened output rows
#define GRID_MAIN 304
#define THREADS 256
#define GUNITS (MGLOB/32)         // 25088 gemm units of 32m x 128i
#define PROWS  (NB*28)            // 28672 prep rows
#define TOTAL_PAIRS (GRID_MAIN*4)

// ticket stream: HEAD prep, then MIDB blocks of [8 prep + 7 gemm], then gemm tail
#define BLOCKS 3584               // PROWS/8
#define LAGB   256
#define HEAD   (8*LAGB)           // 2048
#define MIDB   (BLOCKS-LAGB)      // 3328
#define TICKETS (15*BLOCKS)       // 53760

// ================= scratch =================
__device__ __half g_R[(size_t)PROWS*1024];    // 58.7 MB
__device__ unsigned g_flag[PROWS];            // generation flags (monotonic)
__device__ int g_next;                        // ticket counter
__device__ int g_done;                        // reset coordinator
__device__ unsigned g_cta_ctr;                // monotonic run-id source

// ================= smem layout =================
#define WS_B32    (18*8*32*4)                   // 73728 B
#define WS_BYTES  (WS_B32*4)
#define PBUF_B32  512                           // 2KB: one chunk of 32 rows
#define NBUF      4
#define ACT_BYTES (4*NBUF*PBUF_B32*4)           // 32768 B
#define GSH_OFF   (WS_BYTES + ACT_BYTES)        // 106496
#define SM_TOTAL  (GSH_OFF + 32)

__device__ __forceinline__ void mma_f16(float4& d, const uint4& a, uint32_t b0, uint32_t b1) {
    asm volatile(
        "mma.sync.aligned.m16n8k16.row.col.f32.f16.f16.f32 "
        "{%0,%1,%2,%3}, {%4,%5,%6,%7}, {%8,%9}, {%0,%1,%2,%3};"
        : "+f"(d.x), "+f"(d.y), "+f"(d.z), "+f"(d.w)
        : "r"(a.x), "r"(a.y), "r"(a.z), "r"(a.w), "r"(b0), "r"(b1));
}

#define PAIRBAR(p) asm volatile("bar.sync %0, 64;" :: "r"((p) + 1) : "memory")

// ticket decode
__device__ __forceinline__ void decode_ticket(int t, bool& isprep, int& idx) {
    if (t < HEAD) { isprep = true; idx = t; return; }
    const int q = t - HEAD;
    if (q < 15 * MIDB) {
        const int b = q / 15, r = q - b * 15;
        if (r < 8) { isprep = true;  idx = 8 * (LAGB + b) + r; }
        else       { isprep = false; idx = 7 * b + (r - 8); }
    } else {
        isprep = false; idx = 7 * MIDB + (q - 15 * MIDB);
    }
}

// ================= fused kernel =================
__global__ __launch_bounds__(THREADS, 2) void fused_kernel(const float* __restrict__ x,
                                                           const float* __restrict__ Wg,
                                                           float* __restrict__ out) {
    extern __shared__ char smem[];
    uint32_t* wsb = reinterpret_cast<uint32_t*>(smem);
    const uint4* ws4 = reinterpret_cast<const uint4*>(smem);
    int* gsh = reinterpret_cast<int*>(smem + GSH_OFF);          // [0..3] tickets, [4] run

    const int tid  = threadIdx.x;
    const int lane = tid & 31;
    const int w    = tid >> 5;
    const int warp_i = w & 1;
    const int pair   = w >> 1;
    const int wg   = warp_i * 32 + lane;   // 0..63 within pair
    const int gq   = lane >> 2;
    const int tig  = lane & 3;

    uint32_t* pact = reinterpret_cast<uint32_t*>(smem + WS_BYTES) + pair * (NBUF * PBUF_B32);
    float* xs = reinterpret_cast<float*>(pact);                  // prep scratch (1856 f)

    // run id (same for all CTAs of one launch; monotonic across graph replays)
    if (tid == 0) gsh[4] = (int)(atomicAdd(&g_cta_ctr, 1u) / GRID_MAIN + 1u);

    // ---- weights -> fp16 fragment-ready smem (validated R9-R15) ----
    for (int t = tid; t < WS_B32; t += THREADS) {
        const int reg = t & 3;
        const int ln  = (t >> 2) & 31;
        const int mt  = (t >> 7) & 7;
        const int S   = t >> 10;
        const int r   = (ln >> 2) + ((reg & 1) << 3);
        const int k16 = ((ln & 3) << 1) + ((reg >> 1) << 3);
        const int i   = (mt << 4) + r;
        const int kp  = (S << 4) + k16;
        const int c   = kp >> 5, l = kp & 31;
        const float w0 = Wg[(l * 9 + c) * 128 + i];
        const float w1 = Wg[((l + 1) * 9 + c) * 128 + i];
        const __half2 hv = __floats2half2_rn(w0, w1);
        wsb[t] = *reinterpret_cast<const uint32_t*>(&hv);
    }
    __syncthreads();
    const unsigned run = (unsigned)gsh[4];

    // B-frag swizzled lane offsets
    int lofs[4];
    #pragma unroll
    for (int rr = 0; rr < 4; ++rr)
        lofs[rr] = ((gq ^ (rr << 1)) << 2) + tig;

    // staging identity
    const int srow = lane >> 2;
    const int slot = lane & 3;
    int dstb[2];
    #pragma unroll
    for (int q = 0; q < 2; ++q) {
        const int m_loc = warp_i * 16 + q * 8 + srow;
        dstb[q] = (((slot << 2) + (m_loc >> 3)) << 5)
                + (((m_loc & 7) ^ (slot << 1)) << 2);
    }

    while (true) {
        if (wg == 0) {
            const int t = atomicAdd(&g_next, 1);
            if (t < TICKETS) {
                bool isprep; int idx;
                decode_ticket(t, isprep, idx);
                if (!isprep) {
                    const int mb = idx << 5;
                    int lo = mb / 28 - 1;            if (lo < 0) lo = 0;
                    int hi = (mb + 31) / 28 + 1;     if (hi > PROWS - 1) hi = PROWS - 1;
                    for (int p = lo; p <= hi; ++p) {
                        unsigned v;
                        do {
                            asm volatile("ld.acquire.gpu.global.u32 %0, [%1];"
                                         : "=r"(v) : "l"(g_flag + p));
                        } while (v < run);
                    }
                }
            }
            gsh[pair] = t;
        }
        PAIRBAR(pair);
        const int t = gsh[pair];
        if (t >= TICKETS) break;
        bool isprep; int idx;
        decode_ticket(t, isprep, idx);

        if (isprep) {
            // ========== prep one (n,h') row — MLP-batched loads, scalar STS ==========
            const int n = idx / 28, h = idx - n * 28;
            const float4* xr = reinterpret_cast<const float4*>(x)
                             + ((size_t)(n * 64 + wg) * 28 + h) * 7;
            // 7 independent LDG.128 in flight
            float4 v[7];
            #pragma unroll
            for (int f = 0; f < 7; ++f) v[f] = xr[f];
            // pitch-29 scratch (conflict-free; scalar stores avoid alignment issue)
            float* dst = &xs[wg * 29];
            #pragma unroll
            for (int f = 0; f < 7; ++f) {
                dst[f * 4 + 0] = v[f].x;
                dst[f * 4 + 1] = v[f].y;
                dst[f * 4 + 2] = v[f].z;
                dst[f * 4 + 3] = v[f].w;
            }
            PAIRBAR(pair);
            __half* Rout = g_R + (size_t)idx * 1024;
            const int lp = wg & 15, l0 = lp << 1;
            const int qg = wg >> 4;                 // 0..3
            #pragma unroll
            for (int r = 0; r < 8; ++r) {
                const int q = r * 4 + qg;
                float u0, u1;
                if (q < 28) {
                    int a1 = q - 1; if (a1 < 0) a1 += 28;
                    int a2 = q - 2; if (a2 < 0) a2 += 28;
                    u0 = xs[l0 * 29 + a1] + xs[(32 + l0) * 29 + a2];
                    u1 = xs[(l0 + 1) * 29 + a1] + xs[(33 + l0) * 29 + a2];
                } else if (q == 28) { u0 = xs[(32 + l0) * 29 + 25]; u1 = xs[(33 + l0) * 29 + 25]; }
                else if (q == 29)   { u0 = xs[l0 * 29 + 27];        u1 = xs[(l0 + 1) * 29 + 27]; }
                else if (q == 30)   { u0 = xs[l0 * 29 + 0];         u1 = xs[(l0 + 1) * 29 + 0];  }
                else                { u0 = xs[(32 + l0) * 29 + 26]; u1 = xs[(33 + l0) * 29 + 26]; }
                *reinterpret_cast<__half2*>(&Rout[q * 32 + l0]) = __floats2half2_rn(u0, u1);
            }
            __threadfence();
            PAIRBAR(pair);
            if (wg == 0)
                asm volatile("st.release.gpu.global.u32 [%0], %1;"
                             :: "l"(g_flag + idx), "r"(run) : "memory");
            continue;
        }

        // ================= GEMM unit (validated R12 path) =================
        const int mbase = idx << 5;

        int hq[2], baseq[2], ikp[2];
        #pragma unroll
        for (int q = 0; q < 2; ++q) {
            const int m_loc = warp_i * 16 + q * 8 + srow;
            const int mg = mbase + m_loc;
            const int n  = mg / 784;
            const int r  = mg - n * 784;
            const int h  = r / 28;
            const int wp = r - h * 28;
            hq[q]    = h;
            baseq[q] = (n * 28 + h) << 10;
            const int ik0 = (wp == 0) ? 28 : (wp == 1) ? 29 : (wp - 1);
            const int ik2 = (wp == 0) ? 30 : (wp == 27) ? 31 : (wp + 1);
            ikp[q] = ik0 | (wp << 5) | (ik2 << 10);
        }

        uint4 sv[2];
        #define LDG_CHUNK(cn)  do {                                              \
            const int jj = ((cn) * 11) >> 5;                                     \
            const int kk = (cn) - jj * 3;                                        \
            _Pragma("unroll")                                                    \
            for (int q = 0; q < 2; ++q) {                                        \
                const int hp = hq[q] + jj - 1;                                   \
                const int ik = (ikp[q] >> (kk * 5)) & 31;                        \
                const int off = baseq[q] + ((jj - 1) << 10) + (ik << 5);         \
                sv[q] = make_uint4(0u, 0u, 0u, 0u);                              \
                if ((unsigned)hp < 28u)                                          \
                    sv[q] = *reinterpret_cast<const uint4*>(g_R + off + (slot << 3)); \
            } } while (0)
        #define STS_CHUNK(cn) do {                                               \
            uint32_t* bufn = pact + ((cn) & 3) * PBUF_B32;                       \
            _Pragma("unroll")                                                    \
            for (int q = 0; q < 2; ++q)                                          \
                *reinterpret_cast<uint4*>(bufn + dstb[q]) = sv[q];               \
            } while (0)

        LDG_CHUNK(0); STS_CHUNK(0);
        LDG_CHUNK(1); STS_CHUNK(1);
        LDG_CHUNK(2);
        PAIRBAR(pair);

        float4 acc[4][4];
        #pragma unroll
        for (int a = 0; a < 4; ++a)
            #pragma unroll
            for (int b = 0; b < 4; ++b)
                acc[a][b] = make_float4(0.f, 0.f, 0.f, 0.f);

        #pragma unroll 1
        for (int c = 0; c < 9; ++c) {
            if (c <= 6) STS_CHUNK(c + 2);
            if (c <= 5) LDG_CHUNK(c + 3);

            const uint32_t* bufc = pact + (c & 3) * PBUF_B32;
            #pragma unroll
            for (int s = 0; s < 2; ++s) {
                const int S = c * 2 + s;
                uint4 afr[4];
                #pragma unroll
                for (int mtl = 0; mtl < 4; ++mtl)
                    afr[mtl] = ws4[((S << 3) + warp_i * 4 + mtl) * 32 + lane];
                const int rr0 = s * 2, rr1 = s * 2 + 1;
                uint2 bfr[4];
                #pragma unroll
                for (int ntl = 0; ntl < 4; ++ntl) {
                    bfr[ntl].x = bufc[(((rr0 << 2) + ntl) << 5) + lofs[rr0]];
                    bfr[ntl].y = bufc[(((rr1 << 2) + ntl) << 5) + lofs[rr1]];
                }
                #pragma unroll
                for (int mtl = 0; mtl < 4; ++mtl)
                    #pragma unroll
                    for (int ntl = 0; ntl < 4; ++ntl)
                        mma_f16(acc[mtl][ntl], afr[mtl], bfr[ntl].x, bfr[ntl].y);
            }

            if ((c & 1) || c == 8) PAIRBAR(pair);
        }

        // ---- epilogue: coalesced float2 stores (R12) ----
        #pragma unroll
        for (int mtl = 0; mtl < 4; ++mtl) {
            const int i0 = warp_i * 64 + mtl * 16 + gq;
            #pragma unroll
            for (int ntl = 0; ntl < 4; ++ntl) {
                const int mgo = mbase + ntl * 8 + (tig << 1);
                const int n = mgo / 784;
                const int r = mgo - n * 784;     // float2 never straddles n (mgo even)
                const float4 v = acc[mtl][ntl];
                float* ob = out + (size_t)n * (IIC * 784) + r;
                *reinterpret_cast<float2*>(ob + (size_t)i0 * 784)       = make_float2(v.x, v.y);
                *reinterpret_cast<float2*>(ob + (size_t)(i0 + 8) * 784) = make_float2(v.z, v.w);
            }
        }
        #undef LDG_CHUNK
        #undef STS_CHUNK
    }

    // ---- self-reset of ticket counters (deterministic, graph-replay safe) ----
    if (wg == 0) {
        const int old = atomicAdd(&g_done, 1);
        if (old == TOTAL_PAIRS - 1) {
            g_next = 0;
            __threadfence();
            g_done = 0;
        }
    }
}

// ================= launch =================
extern "C" void kernel_launch(void* const* d_in, const int* in_sizes, int n_in,
                              void* d_out, int out_size) {
    const float* x  = (const float*)d_in[0];   // (1024,64,28,28)
    const float* Wg = (const float*)d_in[1];   // (32,3,3,128)
    float* out = (float*)d_out;                // (1024,128,28,28)

    cudaFuncSetAttribute(fused_kernel, cudaFuncAttributeMaxDynamicSharedMemorySize, SM_TOTAL);
    fused_kernel<<<GRID_MAIN, THREADS, SM_TOTAL>>>(x, Wg, out);
}